// round 1
// baseline (speedup 1.0000x reference)
#include <cuda_runtime.h>
#include <cstdint>

// HighOrderFactorizationMachineModel: BATCH=16384, F=20 fields (dim 50000 each),
// EMBED_DIM=16, ORDER=3. emb_table row = 32 floats: [0:16) order-2 dims,
// [16:32) order-3 dims. Closed forms via power sums:
//   e2 = (p1^2 - p2)/2
//   e3 = (p1^3 - 3 p1 p2 + 2 p3)/6
// One warp per sample; lane l owns row element l -> every emb gather is one
// coalesced 128B line. Lane f (<20) also carries the lin_table gather.

#define FM_BATCH 16384
#define FM_F 20
#define FM_FIELD_DIM 50000

__global__ __launch_bounds__(256)
void fm_ho_kernel(const int* __restrict__ x,
                  const float* __restrict__ emb,
                  const float* __restrict__ lin,
                  const float* __restrict__ bias,
                  float* __restrict__ out)
{
    const int warp = (blockIdx.x * blockDim.x + threadIdx.x) >> 5;
    const int lane = threadIdx.x & 31;
    if (warp >= FM_BATCH) return;

    // Lane f holds the global table index for field f (offsets = f * 50000).
    int gidx = 0;
    float linv = 0.0f;
    if (lane < FM_F) {
        gidx = x[warp * FM_F + lane] + lane * FM_FIELD_DIM;
        linv = __ldg(&lin[gidx]);
    }

    float p1 = 0.0f, p2 = 0.0f, p3 = 0.0f;

    #pragma unroll
    for (int f = 0; f < FM_F; f++) {
        const int idx = __shfl_sync(0xffffffffu, gidx, f);
        const float v = __ldg(&emb[(long)idx * 32 + lane]);
        const float v2 = v * v;
        p1 += v;
        p2 += v2;
        p3 += v2 * v;
    }

    // Lanes 0..15: order-2 dims. Lanes 16..31: order-3 dims.
    float term;
    if (lane < 16) {
        term = 0.5f * (p1 * p1 - p2);
    } else {
        term = (p1 * p1 * p1 - 3.0f * p1 * p2 + 2.0f * p3) * (1.0f / 6.0f);
    }
    term += linv;  // lanes 0..19 contribute linear part, others added 0

    // Warp-wide sum.
    #pragma unroll
    for (int o = 16; o > 0; o >>= 1)
        term += __shfl_xor_sync(0xffffffffu, term, o);

    if (lane == 0)
        out[warp] = term + __ldg(&bias[0]);
}

extern "C" void kernel_launch(void* const* d_in, const int* in_sizes, int n_in,
                              void* d_out, int out_size)
{
    const int*   x    = (const int*)d_in[0];
    const float* emb  = (const float*)d_in[1];
    const float* lin  = (const float*)d_in[2];
    const float* bias = (const float*)d_in[3];
    float*       out  = (float*)d_out;

    // 16384 samples, 1 warp each, 8 warps/block -> 2048 blocks.
    const int threads = 256;
    const int blocks  = (FM_BATCH * 32) / threads;
    fm_ho_kernel<<<blocks, threads>>>(x, emb, lin, bias, out);
}